// round 12
// baseline (speedup 1.0000x reference)
#include <cuda_runtime.h>

// Problem constants
#define B_ROWS 64
#define N_COLS 262144
#define N4 (N_COLS / 4)                 // 65536 float4 per row
#define THREADS 256
#define V4_PER_THREAD 4                 // 16 elements per thread per array
#define F4_PER_BLOCK (THREADS * V4_PER_THREAD)          // 1024 float4
#define BLOCKS_PER_ROW (N4 / F4_PER_BLOCK)              // 64
#define TOTAL_BLOCKS (B_ROWS * BLOCKS_PER_ROW)          // 4096

// Per-block partial, CHUNK-MAJOR: g_part[chunk * B_ROWS + row] = (st, s1, s2, 0).
// Chunk-major makes the last-warp finalize read 32 consecutive slots per LDG
// wave (perfectly coalesced). Every slot overwritten each launch -> no zeroing.
__device__ float4 g_part[TOTAL_BLOCKS];
__device__ unsigned int g_count;        // zero-init at load; reset by last warp

// Release-only arrival (no acquire -> no per-block L1 flush).
__device__ __forceinline__ unsigned int arrive_release(unsigned int* ctr) {
    unsigned int prev;
    asm volatile("atom.add.release.gpu.u32 %0, [%1], 1;"
                 : "=r"(prev) : "l"(ctr) : "memory");
    return prev;
}

__global__ __launch_bounds__(THREADS) void bce_fused_kernel(
    const float4* __restrict__ p4, const float4* __restrict__ t4,
    float* __restrict__ out) {
    const int row = blockIdx.y;
    const int chunk = blockIdx.x;
    const int tid = threadIdx.x;
    const int base = row * N4 + chunk * F4_PER_BLOCK + tid;   // fits in int

    // ---- mainloop: byte-identical to R9 ----
    float4 pv[V4_PER_THREAD], tv[V4_PER_THREAD];
#pragma unroll
    for (int v = 0; v < V4_PER_THREAD; v++) {
        pv[v] = __ldcg(&p4[base + v * THREADS]);
        tv[v] = __ldcg(&t4[base + v * THREADS]);
    }

    float st = 0.f, s1 = 0.f, sq = 0.f, sw = 0.f;
#pragma unroll
    for (int v = 0; v < V4_PER_THREAD; v++) {
        const float pe[4] = {pv[v].x, pv[v].y, pv[v].z, pv[v].w};
        const float te[4] = {tv[v].x, tv[v].y, tv[v].z, tv[v].w};
#pragma unroll
        for (int e = 0; e < 4; e++) {
            float lp = __log2f(pe[e]);            // scaled by ln2 in finalize
            float lq = __log2f(1.0f - pe[e]);
            st += te[e];
            s1 = fmaf(te[e], lp, s1);
            sq += lq;
            sw = fmaf(te[e], lq, sw);
        }
    }
    float s2 = sq - sw;

#pragma unroll
    for (int o = 16; o > 0; o >>= 1) {
        st += __shfl_down_sync(0xFFFFFFFFu, st, o);
        s1 += __shfl_down_sync(0xFFFFFFFFu, s1, o);
        s2 += __shfl_down_sync(0xFFFFFFFFu, s2, o);
    }

    __shared__ float sh_st[THREADS / 32], sh_s1[THREADS / 32], sh_s2[THREADS / 32];
    const int warp = tid >> 5;
    const int lane = tid & 31;
    if (lane == 0) { sh_st[warp] = st; sh_s1[warp] = s1; sh_s2[warp] = s2; }
    __syncthreads();

    // Warps 1-7 are done: they exit here immediately (block resources mostly
    // freed; no second barrier, no is_last broadcast to the whole block).
    if (warp != 0) return;

    // ---- warp-0 tail ----
    const int nw = THREADS / 32;   // 8
    float a = (lane < nw) ? sh_st[lane] : 0.f;
    float b = (lane < nw) ? sh_s1[lane] : 0.f;
    float c = (lane < nw) ? sh_s2[lane] : 0.f;
#pragma unroll
    for (int o = 4; o > 0; o >>= 1) {
        a += __shfl_down_sync(0xFFFFFFFFu, a, o);
        b += __shfl_down_sync(0xFFFFFFFFu, b, o);
        c += __shfl_down_sync(0xFFFFFFFFu, c, o);
    }

    unsigned int prev = 0;
    if (lane == 0) {
        g_part[chunk * B_ROWS + row] = make_float4(a, b, c, 0.f);  // chunk-major
        prev = arrive_release(&g_count);   // releases the store above
    }
    // warp-local broadcast of is_last (no shared, no block barrier)
    unsigned int is_last = __shfl_sync(0xFFFFFFFFu,
                                       (prev == TOTAL_BLOCKS - 1u) ? 1u : 0u, 0);
    if (!is_last) return;

    // ---- finalize: single warp of the last-arriving block ----
    asm volatile("fence.acq_rel.gpu;" ::: "memory");  // one IVALL, once

    // lane l accumulates rows l and l+32; each iteration reads two fully
    // coalesced 512B bursts of L2-hot partials.
    float a0 = 0.f, b0 = 0.f, c0 = 0.f, a1 = 0.f, b1 = 0.f, c1 = 0.f;
#pragma unroll 8
    for (int k = 0; k < BLOCKS_PER_ROW; k++) {
        float4 v0 = g_part[k * B_ROWS + lane];
        float4 v1 = g_part[k * B_ROWS + lane + 32];
        a0 += v0.x; b0 += v0.y; c0 += v0.z;
        a1 += v1.x; b1 += v1.y; c1 += v1.z;
    }

    const double LN2 = 0.6931471805599453;
    double beta0 = 1.0 - (double)a0 / (double)N_COLS;
    double beta1 = 1.0 - (double)a1 / (double)N_COLS;
    double contrib = (beta0 * (double)b0 + (1.0 - beta0) * (double)c0) * LN2
                   + (beta1 * (double)b1 + (1.0 - beta1) * (double)c1) * LN2;

#pragma unroll
    for (int o = 16; o > 0; o >>= 1)
        contrib += __shfl_down_sync(0xFFFFFFFFu, contrib, o);

    if (lane == 0) {
        out[0] = (float)(-contrib);
        *((volatile unsigned int*)&g_count) = 0u;   // reset for next replay
    }
}

extern "C" void kernel_launch(void* const* d_in, const int* in_sizes, int n_in,
                              void* d_out, int out_size) {
    const float4* p = (const float4*)d_in[0];  // input (probabilities)
    const float4* t = (const float4*)d_in[1];  // target
    float* out = (float*)d_out;

    dim3 grid(BLOCKS_PER_ROW, B_ROWS);
    bce_fused_kernel<<<grid, THREADS>>>(p, t, out);
}

// round 13
// speedup vs baseline: 1.3201x; 1.3201x over previous
#include <cuda_runtime.h>
#include <cuda_device_runtime_api.h>

// Problem constants
#define B_ROWS 64
#define N_COLS 262144
#define N4 (N_COLS / 4)                 // 65536 float4 per row
#define THREADS 256
#define V4_PER_THREAD 4                 // 16 elements per thread per array
#define F4_PER_BLOCK (THREADS * V4_PER_THREAD)          // 1024 float4
#define BLOCKS_PER_ROW (N4 / F4_PER_BLOCK)              // 64
#define TOTAL_BLOCKS (B_ROWS * BLOCKS_PER_ROW)          // 4096

// Per-block partial, row-major: g_part[row * BLOCKS_PER_ROW + chunk].
// Every slot overwritten unconditionally each launch -> no zeroing needed.
__device__ float4 g_part[TOTAL_BLOCKS];
__device__ unsigned int g_count;        // zero-init at load; reset by finalizer

__global__ __launch_bounds__(THREADS) void bce_main_kernel(
    const float4* __restrict__ p4, const float4* __restrict__ t4) {
    const int row = blockIdx.y;
    const int chunk = blockIdx.x;
    const int tid = threadIdx.x;
    const int base = row * N4 + chunk * F4_PER_BLOCK + tid;   // fits in int

    // ---- mainloop: byte-identical to R9 (proven 22.3us config) ----
    float4 pv[V4_PER_THREAD], tv[V4_PER_THREAD];
#pragma unroll
    for (int v = 0; v < V4_PER_THREAD; v++) {
        pv[v] = __ldcg(&p4[base + v * THREADS]);
        tv[v] = __ldcg(&t4[base + v * THREADS]);
    }

    float st = 0.f, s1 = 0.f, sq = 0.f, sw = 0.f;
#pragma unroll
    for (int v = 0; v < V4_PER_THREAD; v++) {
        const float pe[4] = {pv[v].x, pv[v].y, pv[v].z, pv[v].w};
        const float te[4] = {tv[v].x, tv[v].y, tv[v].z, tv[v].w};
#pragma unroll
        for (int e = 0; e < 4; e++) {
            float lp = __log2f(pe[e]);            // scaled by ln2 in finalize
            float lq = __log2f(1.0f - pe[e]);
            st += te[e];
            s1 = fmaf(te[e], lp, s1);
            sq += lq;
            sw = fmaf(te[e], lq, sw);
        }
    }
    float s2 = sq - sw;

#pragma unroll
    for (int o = 16; o > 0; o >>= 1) {
        st += __shfl_down_sync(0xFFFFFFFFu, st, o);
        s1 += __shfl_down_sync(0xFFFFFFFFu, s1, o);
        s2 += __shfl_down_sync(0xFFFFFFFFu, s2, o);
    }

    __shared__ float sh_st[THREADS / 32], sh_s1[THREADS / 32], sh_s2[THREADS / 32];
    const int warp = tid >> 5;
    const int lane = tid & 31;
    if (lane == 0) { sh_st[warp] = st; sh_s1[warp] = s1; sh_s2[warp] = s2; }
    __syncthreads();

    if (warp == 0) {
        const int nw = THREADS / 32;   // 8
        float a = (lane < nw) ? sh_st[lane] : 0.f;
        float b = (lane < nw) ? sh_s1[lane] : 0.f;
        float c = (lane < nw) ? sh_s2[lane] : 0.f;
#pragma unroll
        for (int o = 4; o > 0; o >>= 1) {
            a += __shfl_down_sync(0xFFFFFFFFu, a, o);
            b += __shfl_down_sync(0xFFFFFFFFu, b, o);
            c += __shfl_down_sync(0xFFFFFFFFu, c, o);
        }
        if (lane == 0) {
            g_part[row * BLOCKS_PER_ROW + chunk] = make_float4(a, b, c, 0.f);
            // Fire-and-forget arrival: REDG (no return value -> nothing to
            // wait on; block exits immediately). .release orders the STG above.
            asm volatile("red.release.gpu.global.add.u32 [%0], 1;"
                         :: "l"(&g_count) : "memory");
        }
    }
    // no second barrier, no wait: block tail cost == plain-store R9 tail
}

// PDL secondary: launched while the primary runs; spins on the arrival counter
// instead of cudaGridDependencySynchronize, so it finishes ~1 round-trip after
// the LAST PARTIAL lands rather than after the primary's full end-of-grid drain.
__global__ __launch_bounds__(256) void finalize_kernel(float* __restrict__ out) {
    const int tid = threadIdx.x;

    if (tid == 0) {
        unsigned int c;
        do {
            asm volatile("ld.acquire.gpu.global.u32 %0, [%1];"
                         : "=r"(c) : "l"(&g_count) : "memory");
            if (c == TOTAL_BLOCKS) break;
            __nanosleep(64);
        } while (1);
    }
    __syncthreads();   // all threads ordered after the acquire-load

    // 4 threads per row x 64 rows = 256 threads; 16 partials per thread.
    const int r = tid >> 2;            // 0..63
    const int sub = tid & 3;           // 0..3

    float a = 0.f, b = 0.f, c = 0.f;
#pragma unroll
    for (int k = 0; k < BLOCKS_PER_ROW / 4; k++) {   // 16 iters
        float4 v = g_part[r * BLOCKS_PER_ROW + sub + k * 4];
        a += v.x; b += v.y; c += v.z;
    }
#pragma unroll
    for (int o = 2; o > 0; o >>= 1) {
        a += __shfl_down_sync(0xFFFFFFFFu, a, o, 4);
        b += __shfl_down_sync(0xFFFFFFFFu, b, o, 4);
        c += __shfl_down_sync(0xFFFFFFFFu, c, o, 4);
    }

    __shared__ double sh_row[B_ROWS];
    if (sub == 0) {
        const double LN2 = 0.6931471805599453;
        double beta = 1.0 - (double)a / (double)N_COLS;
        sh_row[r] = (beta * (double)b + (1.0 - beta) * (double)c) * LN2;
    }
    __syncthreads();

    if (tid < 64) {
        double s = sh_row[tid];
#pragma unroll
        for (int o = 16; o > 0; o >>= 1)
            s += __shfl_down_sync(0xFFFFFFFFu, s, o);
        __shared__ double sh2[2];
        if ((tid & 31) == 0) sh2[tid >> 5] = s;
        __syncthreads();
        if (tid == 0) {
            out[0] = (float)(-(sh2[0] + sh2[1]));
            g_count = 0;               // reset for next graph replay
        }
    }
}

extern "C" void kernel_launch(void* const* d_in, const int* in_sizes, int n_in,
                              void* d_out, int out_size) {
    const float4* p = (const float4*)d_in[0];  // input (probabilities)
    const float4* t = (const float4*)d_in[1];  // target
    float* out = (float*)d_out;

    dim3 grid(BLOCKS_PER_ROW, B_ROWS);
    bce_main_kernel<<<grid, THREADS>>>(p, t);

    // Programmatic dependent launch: secondary may be scheduled while the
    // primary is still draining; it self-synchronizes via g_count.
    cudaLaunchConfig_t cfg = {};
    cfg.gridDim = dim3(1, 1, 1);
    cfg.blockDim = dim3(256, 1, 1);
    cfg.dynamicSmemBytes = 0;
    cfg.stream = 0;
    cudaLaunchAttribute attrs[1];
    attrs[0].id = cudaLaunchAttributeProgrammaticStreamSerialization;
    attrs[0].val.programmaticStreamSerializationAllowed = 1;
    cfg.attrs = attrs;
    cfg.numAttrs = 1;
    cudaLaunchKernelEx(&cfg, finalize_kernel, out);
}